// round 8
// baseline (speedup 1.0000x reference)
#include <cuda_runtime.h>
#include <stdint.h>

// Problem constants (fixed by the dataset)
#define NN 100000      // nodes
#define EE 1600000     // edges
#define F0 128
#define F1 64
#define F2 40

// ---------------- scratch (static device globals; allocation-free) ----------
__device__ __align__(16) float g_h1s [NN * F1];   // (x @ W1) * invsqrt[row]
__device__ __align__(16) float g_out1[NN * F1];   // relu(invsqrt*(gather + self))
__device__ __align__(16) float g_h2s [NN * F2];   // (out1 @ W2) * invsqrt[row]
__device__ int   g_deg[NN];
__device__ int   g_off[NN + 1];
__device__ int   g_cursor[NN];
__device__ int   g_csr_src[EE];                   // edge srcs grouped by dst
__device__ float g_invsqrt[NN];

// ---------------- kernels ---------------------------------------------------

__global__ void zero_kernel() {
    int i = blockIdx.x * blockDim.x + threadIdx.x;
    if (i < NN) g_deg[i] = 0;
}

// Degree histogram over dst; 2 edges per thread for atomic MLP.
__global__ void deg_kernel(const int* __restrict__ dst, int E) {
    int i = (blockIdx.x * blockDim.x + threadIdx.x) * 2;
    if (i + 1 < E) {
        int2 d = *reinterpret_cast<const int2*>(dst + i);
        atomicAdd(&g_deg[d.x], 1);
        atomicAdd(&g_deg[d.y], 1);
    } else if (i < E) {
        atomicAdd(&g_deg[dst[i]], 1);
    }
}

// Single-block exclusive prefix scan of g_deg -> g_off / g_cursor, fused with
// invsqrt. 1024 threads, each owns a contiguous chunk of ~98 nodes.
__global__ __launch_bounds__(1024) void prefix_kernel() {
    __shared__ int ssum[1024];
    const int CH = (NN + 1023) / 1024;   // 98
    int t = threadIdx.x;
    int b = t * CH;
    int e = b + CH < NN ? b + CH : NN;
    if (b > NN) b = NN;

    int s = 0;
    for (int i = b; i < e; ++i) s += g_deg[i];
    ssum[t] = s;
    __syncthreads();

    for (int off = 1; off < 1024; off <<= 1) {
        int v = (t >= off) ? ssum[t - off] : 0;
        __syncthreads();
        ssum[t] += v;
        __syncthreads();
    }

    int run = ssum[t] - s;               // exclusive start of this chunk
    for (int i = b; i < e; ++i) {
        g_off[i]    = run;
        g_cursor[i] = run;
        int d = g_deg[i];
        run += d;
        g_invsqrt[i] = rsqrtf((float)(d + 1));
    }
    if (t == 1023) g_off[NN] = ssum[1023];
}

// Fill CSR: group edge srcs by dst via cursor atomics; 2 edges per thread.
__global__ void fill_kernel(const int* __restrict__ src,
                            const int* __restrict__ dst, int E) {
    int i = (blockIdx.x * blockDim.x + threadIdx.x) * 2;
    if (i + 1 < E) {
        int2 d = *reinterpret_cast<const int2*>(dst + i);
        int2 s = *reinterpret_cast<const int2*>(src + i);
        int p0 = atomicAdd(&g_cursor[d.x], 1);
        int p1 = atomicAdd(&g_cursor[d.y], 1);
        g_csr_src[p0] = s.x;
        g_csr_src[p1] = s.y;
    } else if (i < E) {
        int pos = atomicAdd(&g_cursor[dst[i]], 1);
        g_csr_src[pos] = src[i];
    }
}

// h1s = (x @ W1) * invsqrt[row]   (100000x128 @ 128x64), fp32.
// Tiled GEMM (verified R7): 256 threads, 64x64 tile, 4x4 micro-tile, k-chunked.
__global__ __launch_bounds__(256) void gemm1_kernel(const float* __restrict__ x,
                                                    const float* __restrict__ W1) {
    __shared__ float sX[64][68];            // [k_local][row], padded pitch
    __shared__ float sW[64 * F1];           // [k_local][col] chunk, 16 KB
    int tid = threadIdx.x;
    int row0 = blockIdx.x * 64;

    int tx = tid & 15;
    int ty = tid >> 4;

    float acc[4][4];
    #pragma unroll
    for (int r = 0; r < 4; ++r)
        #pragma unroll
        for (int c = 0; c < 4; ++c) acc[r][c] = 0.f;

    #pragma unroll
    for (int kc = 0; kc < 2; ++kc) {
        int k0 = kc * 64;

        const float4* w4g = reinterpret_cast<const float4*>(W1 + k0 * F1);
        #pragma unroll
        for (int i = 0; i < 4; ++i)
            reinterpret_cast<float4*>(sW)[tid + i * 256] = w4g[tid + i * 256];

        #pragma unroll
        for (int i = 0; i < 4; ++i) {
            int idx = tid + i * 256;
            int r   = idx >> 4;
            int k4  = idx & 15;
            int rr = row0 + r; if (rr >= NN) rr = NN - 1;
            float4 v = reinterpret_cast<const float4*>(
                           x + (size_t)rr * F0 + k0)[k4];
            sX[k4 * 4 + 0][r] = v.x;
            sX[k4 * 4 + 1][r] = v.y;
            sX[k4 * 4 + 2][r] = v.z;
            sX[k4 * 4 + 3][r] = v.w;
        }
        __syncthreads();

        #pragma unroll 4
        for (int k = 0; k < 64; ++k) {
            float4 xv = *reinterpret_cast<const float4*>(&sX[k][ty * 4]);
            float4 wv = *reinterpret_cast<const float4*>(&sW[k * F1 + tx * 4]);
            float xa[4] = {xv.x, xv.y, xv.z, xv.w};
            float wa[4] = {wv.x, wv.y, wv.z, wv.w};
            #pragma unroll
            for (int r = 0; r < 4; ++r)
                #pragma unroll
                for (int c = 0; c < 4; ++c)
                    acc[r][c] = fmaf(xa[r], wa[c], acc[r][c]);
        }
        __syncthreads();
    }

    #pragma unroll
    for (int r = 0; r < 4; ++r) {
        int rr = row0 + ty * 4 + r;
        if (rr < NN) {
            float sc = g_invsqrt[rr];
            *reinterpret_cast<float4*>(g_h1s + (size_t)rr * F1 + tx * 4) =
                make_float4(acc[r][0] * sc, acc[r][1] * sc,
                            acc[r][2] * sc, acc[r][3] * sc);
        }
    }
}

// Layer-1 aggregation (CSR gather, atomic-free), fused self + relu.
// Warp per node, lane owns features [2*lane, 2*lane+1], 8 edges in flight.
__global__ __launch_bounds__(256) void agg1_kernel() {
    int node = (blockIdx.x * 256 + threadIdx.x) >> 5;
    int lane = threadIdx.x & 31;
    if (node >= NN) return;

    int beg = g_off[node];
    int end = g_off[node + 1];
    float inv_d = g_invsqrt[node];

    const float2* h1f = reinterpret_cast<const float2*>(g_h1s);
    float2 a0 = make_float2(0.f, 0.f);
    float2 a1 = make_float2(0.f, 0.f);
    float2 a2 = make_float2(0.f, 0.f);
    float2 a3 = make_float2(0.f, 0.f);

    int e = beg;
    for (; e + 8 <= end; e += 8) {
        int s0 = __ldg(g_csr_src + e + 0);
        int s1 = __ldg(g_csr_src + e + 1);
        int s2 = __ldg(g_csr_src + e + 2);
        int s3 = __ldg(g_csr_src + e + 3);
        int s4 = __ldg(g_csr_src + e + 4);
        int s5 = __ldg(g_csr_src + e + 5);
        int s6 = __ldg(g_csr_src + e + 6);
        int s7 = __ldg(g_csr_src + e + 7);
        float2 v0 = h1f[(size_t)s0 * 32 + lane];
        float2 v1 = h1f[(size_t)s1 * 32 + lane];
        float2 v2 = h1f[(size_t)s2 * 32 + lane];
        float2 v3 = h1f[(size_t)s3 * 32 + lane];
        float2 v4 = h1f[(size_t)s4 * 32 + lane];
        float2 v5 = h1f[(size_t)s5 * 32 + lane];
        float2 v6 = h1f[(size_t)s6 * 32 + lane];
        float2 v7 = h1f[(size_t)s7 * 32 + lane];
        a0.x += v0.x + v4.x; a0.y += v0.y + v4.y;
        a1.x += v1.x + v5.x; a1.y += v1.y + v5.y;
        a2.x += v2.x + v6.x; a2.y += v2.y + v6.y;
        a3.x += v3.x + v7.x; a3.y += v3.y + v7.y;
    }
    for (; e < end; ++e) {
        int s0 = __ldg(g_csr_src + e);
        float2 v0 = h1f[(size_t)s0 * 32 + lane];
        a0.x += v0.x; a0.y += v0.y;
    }

    float2 h = h1f[(size_t)node * 32 + lane];
    float2 o;
    o.x = fmaxf(inv_d * (a0.x + a1.x + a2.x + a3.x + h.x), 0.f);
    o.y = fmaxf(inv_d * (a0.y + a1.y + a2.y + a3.y + h.y), 0.f);
    reinterpret_cast<float2*>(g_out1)[(size_t)node * 32 + lane] = o;
}

// h2s = (out1 @ W2) * invsqrt[row]  (64 -> 40). Thread per row, W2 in SMEM.
__global__ __launch_bounds__(128) void gemm2_kernel(const float* __restrict__ W2) {
    __shared__ float sW[F1 * F2];           // 10.25 KB
    int tid = threadIdx.x;
    for (int i = tid; i < F1 * F2; i += 128) sW[i] = W2[i];
    __syncthreads();

    int row = blockIdx.x * 128 + tid;
    if (row >= NN) return;

    float acc[F2];
    #pragma unroll
    for (int j = 0; j < F2; ++j) acc[j] = 0.f;

    const float4* orow = reinterpret_cast<const float4*>(g_out1 + (size_t)row * F1);
    #pragma unroll 2
    for (int k4 = 0; k4 < F1 / 4; ++k4) {
        float4 ov = orow[k4];
        float oa[4] = {ov.x, ov.y, ov.z, ov.w};
        #pragma unroll
        for (int kk = 0; kk < 4; ++kk) {
            float os = oa[kk];
            const float4* w4 = reinterpret_cast<const float4*>(sW + (k4 * 4 + kk) * F2);
            #pragma unroll
            for (int j = 0; j < F2 / 4; ++j) {
                float4 w = w4[j];
                acc[4*j+0] = fmaf(os, w.x, acc[4*j+0]);
                acc[4*j+1] = fmaf(os, w.y, acc[4*j+1]);
                acc[4*j+2] = fmaf(os, w.z, acc[4*j+2]);
                acc[4*j+3] = fmaf(os, w.w, acc[4*j+3]);
            }
        }
    }
    float inv_d = g_invsqrt[row];
    float4* out = reinterpret_cast<float4*>(g_h2s + (size_t)row * F2);
    #pragma unroll
    for (int j = 0; j < F2 / 4; ++j)
        out[j] = make_float4(acc[4*j]*inv_d, acc[4*j+1]*inv_d,
                             acc[4*j+2]*inv_d, acc[4*j+3]*inv_d);
}

// Layer-2 aggregation (CSR gather) fused self + relu -> d_out.
// Warp per node; lane owns feature `lane`, + feature 32+lane if lane<8.
__global__ __launch_bounds__(256) void agg2_kernel(float* __restrict__ out) {
    int node = (blockIdx.x * 256 + threadIdx.x) >> 5;
    int lane = threadIdx.x & 31;
    if (node >= NN) return;

    int beg = g_off[node];
    int end = g_off[node + 1];
    float inv_d = g_invsqrt[node];
    bool hi = (lane < 8);

    float aa0 = 0.f, aa1 = 0.f, aa2 = 0.f, aa3 = 0.f;
    float ab0 = 0.f, ab1 = 0.f, ab2 = 0.f, ab3 = 0.f;

    int e = beg;
    for (; e + 8 <= end; e += 8) {
        int s0 = __ldg(g_csr_src + e + 0);
        int s1 = __ldg(g_csr_src + e + 1);
        int s2 = __ldg(g_csr_src + e + 2);
        int s3 = __ldg(g_csr_src + e + 3);
        int s4 = __ldg(g_csr_src + e + 4);
        int s5 = __ldg(g_csr_src + e + 5);
        int s6 = __ldg(g_csr_src + e + 6);
        int s7 = __ldg(g_csr_src + e + 7);
        const float* r0 = g_h2s + (size_t)s0 * F2;
        const float* r1 = g_h2s + (size_t)s1 * F2;
        const float* r2 = g_h2s + (size_t)s2 * F2;
        const float* r3 = g_h2s + (size_t)s3 * F2;
        const float* r4 = g_h2s + (size_t)s4 * F2;
        const float* r5 = g_h2s + (size_t)s5 * F2;
        const float* r6 = g_h2s + (size_t)s6 * F2;
        const float* r7 = g_h2s + (size_t)s7 * F2;
        float va0 = r0[lane], va1 = r1[lane], va2 = r2[lane], va3 = r3[lane];
        float va4 = r4[lane], va5 = r5[lane], va6 = r6[lane], va7 = r7[lane];
        float vb0 = hi ? r0[32+lane] : 0.f, vb1 = hi ? r1[32+lane] : 0.f;
        float vb2 = hi ? r2[32+lane] : 0.f, vb3 = hi ? r3[32+lane] : 0.f;
        float vb4 = hi ? r4[32+lane] : 0.f, vb5 = hi ? r5[32+lane] : 0.f;
        float vb6 = hi ? r6[32+lane] : 0.f, vb7 = hi ? r7[32+lane] : 0.f;
        aa0 += va0 + va4; aa1 += va1 + va5;
        aa2 += va2 + va6; aa3 += va3 + va7;
        ab0 += vb0 + vb4; ab1 += vb1 + vb5;
        ab2 += vb2 + vb6; ab3 += vb3 + vb7;
    }
    for (; e < end; ++e) {
        int s0 = __ldg(g_csr_src + e);
        const float* r0 = g_h2s + (size_t)s0 * F2;
        aa0 += r0[lane];
        if (hi) ab0 += r0[32 + lane];
    }

    const float* hrow = g_h2s + (size_t)node * F2;
    float* orow = out + (size_t)node * F2;
    orow[lane] = fmaxf(inv_d * (aa0 + aa1 + aa2 + aa3 + hrow[lane]), 0.f);
    if (hi)
        orow[32 + lane] = fmaxf(inv_d * (ab0 + ab1 + ab2 + ab3 + hrow[32 + lane]), 0.f);
}

// ---------------- launch ----------------------------------------------------
extern "C" void kernel_launch(void* const* d_in, const int* in_sizes, int n_in,
                              void* d_out, int out_size) {
    const float* x  = (const float*)d_in[0];   // [N,128]
    const int*   ei = (const int*)  d_in[1];   // [2,E]
    const float* W1 = (const float*)d_in[2];   // [128,64]
    const float* W2 = (const float*)d_in[3];   // [64,40]
    float* out = (float*)d_out;

    int E = in_sizes[1] / 2;
    const int* src = ei;
    const int* dst = ei + E;

    // CSR build (by dst) + norms
    zero_kernel  <<<(NN + 255) / 256, 256>>>();
    deg_kernel   <<<(E/2 + 255) / 256, 256>>>(dst, E);
    prefix_kernel<<<1, 1024>>>();
    fill_kernel  <<<(E/2 + 255) / 256, 256>>>(src, dst, E);

    // layer 1
    gemm1_kernel <<<(NN + 63) / 64, 256>>>(x, W1);       // h1s
    agg1_kernel  <<<(NN * 32 + 255) / 256, 256>>>();     // out1 (gather, no atomics)

    // layer 2
    gemm2_kernel <<<(NN + 127) / 128, 128>>>(W2);        // h2s
    agg2_kernel  <<<(NN * 32 + 255) / 256, 256>>>(out);  // final (gather, no atomics)
}